// round 16
// baseline (speedup 1.0000x reference)
#include <cuda_runtime.h>

// Net_32521492365587 — tiny LSTM ensemble + dense decode, single scalar output.
//
// FINAL KERNEL (16 rounds of evidence):
//   out = (W1^T·W2)·feat + (W2·b1 + b2)   [no nonlinearity between W1 and W2]
//   - v = W1^T·W2 and c = W2.b1+b2 computed by dedicated warps concurrently
//     with the LSTM gate phase; ONE __syncthreads total.
//   - opp LSTM starts from zero state: W_hh_opp (40KB) never read, f-gate dead.
//   - all roles warp-aligned (no warp carries two heavy branch arms).
//   - activations: EX2 + rcp.approx.f32 (single MUFU); measured rel_err 8.7e-8.
//   - v-halves split so each thread's loads are fully unrolled & independent
//     (one overlapped memory-latency wave).
//   - tail: dual accumulator chains + early b2 load (latency overlap).
//
// Thread plan (544 threads, 17 warps):
//   warps  0..3  : gen gate lanes (tid<100)  -> s_feat[0..99]
//   warps  4..5  : opp gate lanes (o<50)     -> s_feat[100..149]
//   warps  6..10 : v-half0 (m 0..37)         -> s_v0[i]
//   warps 11..15 : v-half1 (m 38..74)        -> s_v1[i]
//   warp  16     : c = W2.b1+b2 (regs); post-bar final dot -> out

__device__ __forceinline__ float rcp_approx(float x) {
    float r;
    asm("rcp.approx.f32 %0, %1;" : "=f"(r) : "f"(x));
    return r;
}

__device__ __forceinline__ float sigmoid_f(float v) {
    // 1/(1+e^-v): EX2 + MUFU.RCP (no Newton fixups)
    return rcp_approx(1.0f + __expf(-v));
}

__device__ __forceinline__ float tanh_f(float v) {
    // tanh(v) = 1 - 2/(e^(2v)+1): EX2 + MUFU.RCP, branch-free
    const float e = __expf(2.0f * v);
    return fmaf(-2.0f, rcp_approx(e + 1.0f), 1.0f);
}

__device__ __forceinline__ float warp_sum(float v) {
    #pragma unroll
    for (int off = 16; off; off >>= 1)
        v += __shfl_xor_sync(0xffffffffu, v, off);
    return v;
}

__global__ __launch_bounds__(544, 1)
void net_kernel(const float* __restrict__ x,
                const float* __restrict__ h0_gen,
                const float* __restrict__ c0_gen,
                const float* __restrict__ W_ih_opp,
                const float* __restrict__ b_ih_opp,
                const float* __restrict__ b_hh_opp,
                const float* __restrict__ W_ih_gen,
                const float* __restrict__ W_hh_gen,
                const float* __restrict__ b_ih_gen,
                const float* __restrict__ b_hh_gen,
                const float* __restrict__ W1,
                const float* __restrict__ b1,
                const float* __restrict__ W2,
                const float* __restrict__ b2,
                float* __restrict__ out)
{
    __shared__ float s_feat[152];
    __shared__ float s_v0[152];
    __shared__ float s_v1[152];

    const int tid  = threadIdx.x;
    const int warp = tid >> 5;
    const int lane = tid & 31;

    float c_reg = 0.0f;            // live only in warp 16

    if (warp < 4) {
        // ================= gen lanes (tid 0..99) =============================
        if (tid < 100) {
            const int g = tid / 10;
            const int j = tid - g * 10;

            const float4 xv0 = reinterpret_cast<const float4*>(x)[0];
            const float4 xv1 = reinterpret_cast<const float4*>(x)[1];
            float2 h2[5];
            const float2* __restrict__ h0p = reinterpret_cast<const float2*>(h0_gen + g * 10);
            #pragma unroll
            for (int k = 0; k < 5; ++k) h2[k] = h0p[k];
            const float c0v = c0_gen[tid];

            float gate[4];
            #pragma unroll
            for (int k = 0; k < 4; ++k) {
                const int row = g * 40 + k * 10 + j;
                const float4* __restrict__ wi = reinterpret_cast<const float4*>(W_ih_gen + row * 8);
                const float2* __restrict__ wh = reinterpret_cast<const float2*>(W_hh_gen + row * 10);
                float acc = b_ih_gen[row] + b_hh_gen[row];
                const float4 a = wi[0], b = wi[1];
                acc = fmaf(a.x, xv0.x, acc); acc = fmaf(a.y, xv0.y, acc);
                acc = fmaf(a.z, xv0.z, acc); acc = fmaf(a.w, xv0.w, acc);
                acc = fmaf(b.x, xv1.x, acc); acc = fmaf(b.y, xv1.y, acc);
                acc = fmaf(b.z, xv1.z, acc); acc = fmaf(b.w, xv1.w, acc);
                #pragma unroll
                for (int kk = 0; kk < 5; ++kk) {
                    const float2 w = wh[kk];
                    acc = fmaf(w.x, h2[kk].x, acc);
                    acc = fmaf(w.y, h2[kk].y, acc);
                }
                gate[k] = acc;
            }
            // gate order i,f,g,o
            const float c2 = sigmoid_f(gate[1]) * c0v + sigmoid_f(gate[0]) * tanh_f(gate[2]);
            s_feat[tid] = sigmoid_f(gate[3]) * tanh_f(c2);
        }
    } else if (warp < 6) {
        // ================= opp lanes (o = tid-128, active o<50) ==============
        // zero initial state -> f-gate dead, c2 = sig(i)*tanh(g)
        const int o = tid - 128;
        if (o < 50) {
            const float4 xv0 = reinterpret_cast<const float4*>(x)[0];
            const float4 xv1 = reinterpret_cast<const float4*>(x)[1];
            const int rows[3] = { o, 100 + o, 150 + o };   // i, g, o rows
            float gv[3];
            #pragma unroll
            for (int k = 0; k < 3; ++k) {
                const int row = rows[k];
                const float4* __restrict__ w = reinterpret_cast<const float4*>(W_ih_opp + row * 8);
                float acc = b_ih_opp[row] + b_hh_opp[row];
                const float4 a = w[0], b = w[1];
                acc = fmaf(a.x, xv0.x, acc); acc = fmaf(a.y, xv0.y, acc);
                acc = fmaf(a.z, xv0.z, acc); acc = fmaf(a.w, xv0.w, acc);
                acc = fmaf(b.x, xv1.x, acc); acc = fmaf(b.y, xv1.y, acc);
                acc = fmaf(b.z, xv1.z, acc); acc = fmaf(b.w, xv1.w, acc);
                gv[k] = acc;
            }
            const float c2 = sigmoid_f(gv[0]) * tanh_f(gv[1]);
            s_feat[100 + o] = sigmoid_f(gv[2]) * tanh_f(c2);
        }
    } else if (warp < 11) {
        // ---- v-half0: sum_{m=0}^{37} W2[m]*W1[m,i], FULL unroll ----
        const int i = tid - 192;
        if (i < 150) {
            const float* __restrict__ w1c = W1 + i;
            float acc = 0.0f;
            #pragma unroll
            for (int m = 0; m < 38; ++m)
                acc = fmaf(__ldg(W2 + m), w1c[m * 150], acc);
            s_v0[i] = acc;
        }
    } else if (warp < 16) {
        // ---- v-half1: sum_{m=38}^{74} W2[m]*W1[m,i], FULL unroll ----
        const int i = tid - 352;
        if (i < 150) {
            const float* __restrict__ w1c = W1 + 38 * 150 + i;
            float acc = 0.0f;
            #pragma unroll
            for (int m = 0; m < 37; ++m)
                acc = fmaf(__ldg(W2 + 38 + m), w1c[m * 150], acc);
            s_v1[i] = acc;
        }
    } else {
        // ---- warp 16: c = W2.b1 + b2, kept in registers ----
        const float b2v = __ldg(b2);          // issued first: overlaps the dot
        float acc = 0.0f;
        #pragma unroll
        for (int m = lane; m < 75; m += 32)
            acc = fmaf(W2[m], b1[m], acc);
        c_reg = warp_sum(acc) + b2v;
    }
    __syncthreads();

    // ---- tail: out = sum_i (v0[i]+v1[i])*feat[i] + c   (warp 16) ----
    // dual accumulator chains: halves the dependent FMA depth before the tree
    if (warp == 16) {
        float a0 = 0.0f, a1 = 0.0f;
        {
            const int i = lane;
            a0 = fmaf(s_v0[i] + s_v1[i], s_feat[i], a0);
        }
        {
            const int i = lane + 32;
            a1 = fmaf(s_v0[i] + s_v1[i], s_feat[i], a1);
        }
        {
            const int i = lane + 64;
            a0 = fmaf(s_v0[i] + s_v1[i], s_feat[i], a0);
        }
        {
            const int i = lane + 96;
            a1 = fmaf(s_v0[i] + s_v1[i], s_feat[i], a1);
        }
        if (lane < 22) {
            const int i = lane + 128;
            a0 = fmaf(s_v0[i] + s_v1[i], s_feat[i], a0);
        }
        float acc = warp_sum(a0 + a1);
        if (lane == 0) out[0] = acc + c_reg;
    }
}

extern "C" void kernel_launch(void* const* d_in, const int* in_sizes, int n_in,
                              void* d_out, int out_size)
{
    const float* x        = (const float*)d_in[0];
    const float* h0_gen   = (const float*)d_in[1];
    const float* c0_gen   = (const float*)d_in[2];
    const float* W_ih_opp = (const float*)d_in[3];
    // d_in[4] = W_hh_opp — unused (zero initial state)
    const float* b_ih_opp = (const float*)d_in[5];
    const float* b_hh_opp = (const float*)d_in[6];
    const float* W_ih_gen = (const float*)d_in[7];
    const float* W_hh_gen = (const float*)d_in[8];
    const float* b_ih_gen = (const float*)d_in[9];
    const float* b_hh_gen = (const float*)d_in[10];
    const float* W1       = (const float*)d_in[11];
    const float* b1       = (const float*)d_in[12];
    const float* W2       = (const float*)d_in[13];
    const float* b2       = (const float*)d_in[14];
    float* out = (float*)d_out;

    net_kernel<<<1, 544>>>(x, h0_gen, c0_gen, W_ih_opp, b_ih_opp, b_hh_opp,
                           W_ih_gen, W_hh_gen, b_ih_gen, b_hh_gen,
                           W1, b1, W2, b2, out);
}

// round 17
// speedup vs baseline: 1.0761x; 1.0761x over previous
#include <cuda_runtime.h>

// Net_32521492365587 — tiny LSTM ensemble + dense decode, single scalar output.
//
// CONVERGED FINAL KERNEL (17 rounds):
//   out = (W1^T·W2)·feat + (W2·b1 + b2)   [no nonlinearity between W1 and W2]
//   - v = W1^T·W2 and c = W2.b1+b2 computed by dedicated warps concurrently
//     with the LSTM gate phase; ONE __syncthreads total.
//   - opp LSTM starts from zero state: W_hh_opp (40KB) never read, f-gate dead.
//   - all roles warp-aligned (no warp carries two heavy branch arms).
//   - activations: EX2 + rcp.approx.f32 (single MUFU); measured rel_err 8.7e-8.
//   - v-halves split so each thread's loads are fully unrolled & independent
//     (one overlapped memory-latency wave).
//
// Thread plan (544 threads, 17 warps):
//   warps  0..3  : gen gate lanes (tid<100)  -> s_feat[0..99]
//   warps  4..5  : opp gate lanes (o<50)     -> s_feat[100..149]
//   warps  6..10 : v-half0 (m 0..37)         -> s_v0[i]
//   warps 11..15 : v-half1 (m 38..74)        -> s_v1[i]
//   warp  16     : c = W2.b1+b2 (regs); post-bar final dot -> out

__device__ __forceinline__ float rcp_approx(float x) {
    float r;
    asm("rcp.approx.f32 %0, %1;" : "=f"(r) : "f"(x));
    return r;
}

__device__ __forceinline__ float sigmoid_f(float v) {
    // 1/(1+e^-v): EX2 + MUFU.RCP (no IEEE Newton fixups)
    return rcp_approx(1.0f + __expf(-v));
}

__device__ __forceinline__ float tanh_f(float v) {
    // tanh(v) = 1 - 2/(e^(2v)+1): EX2 + MUFU.RCP, branch-free
    const float e = __expf(2.0f * v);
    return fmaf(-2.0f, rcp_approx(e + 1.0f), 1.0f);
}

__device__ __forceinline__ float warp_sum(float v) {
    #pragma unroll
    for (int off = 16; off; off >>= 1)
        v += __shfl_xor_sync(0xffffffffu, v, off);
    return v;
}

__global__ __launch_bounds__(544, 1)
void net_kernel(const float* __restrict__ x,
                const float* __restrict__ h0_gen,
                const float* __restrict__ c0_gen,
                const float* __restrict__ W_ih_opp,
                const float* __restrict__ b_ih_opp,
                const float* __restrict__ b_hh_opp,
                const float* __restrict__ W_ih_gen,
                const float* __restrict__ W_hh_gen,
                const float* __restrict__ b_ih_gen,
                const float* __restrict__ b_hh_gen,
                const float* __restrict__ W1,
                const float* __restrict__ b1,
                const float* __restrict__ W2,
                const float* __restrict__ b2,
                float* __restrict__ out)
{
    __shared__ float s_feat[152];
    __shared__ float s_v0[152];
    __shared__ float s_v1[152];

    const int tid  = threadIdx.x;
    const int warp = tid >> 5;
    const int lane = tid & 31;

    float c_reg = 0.0f;            // live only in warp 16

    if (warp < 4) {
        // ================= gen lanes (tid 0..99) =============================
        if (tid < 100) {
            const int g = tid / 10;
            const int j = tid - g * 10;

            const float4 xv0 = reinterpret_cast<const float4*>(x)[0];
            const float4 xv1 = reinterpret_cast<const float4*>(x)[1];
            float2 h2[5];
            const float2* __restrict__ h0p = reinterpret_cast<const float2*>(h0_gen + g * 10);
            #pragma unroll
            for (int k = 0; k < 5; ++k) h2[k] = h0p[k];
            const float c0v = c0_gen[tid];

            float gate[4];
            #pragma unroll
            for (int k = 0; k < 4; ++k) {
                const int row = g * 40 + k * 10 + j;
                const float4* __restrict__ wi = reinterpret_cast<const float4*>(W_ih_gen + row * 8);
                const float2* __restrict__ wh = reinterpret_cast<const float2*>(W_hh_gen + row * 10);
                float acc = b_ih_gen[row] + b_hh_gen[row];
                const float4 a = wi[0], b = wi[1];
                acc = fmaf(a.x, xv0.x, acc); acc = fmaf(a.y, xv0.y, acc);
                acc = fmaf(a.z, xv0.z, acc); acc = fmaf(a.w, xv0.w, acc);
                acc = fmaf(b.x, xv1.x, acc); acc = fmaf(b.y, xv1.y, acc);
                acc = fmaf(b.z, xv1.z, acc); acc = fmaf(b.w, xv1.w, acc);
                #pragma unroll
                for (int kk = 0; kk < 5; ++kk) {
                    const float2 w = wh[kk];
                    acc = fmaf(w.x, h2[kk].x, acc);
                    acc = fmaf(w.y, h2[kk].y, acc);
                }
                gate[k] = acc;
            }
            // gate order i,f,g,o
            const float c2 = sigmoid_f(gate[1]) * c0v + sigmoid_f(gate[0]) * tanh_f(gate[2]);
            s_feat[tid] = sigmoid_f(gate[3]) * tanh_f(c2);
        }
    } else if (warp < 6) {
        // ================= opp lanes (o = tid-128, active o<50) ==============
        // zero initial state -> f-gate dead, c2 = sig(i)*tanh(g)
        const int o = tid - 128;
        if (o < 50) {
            const float4 xv0 = reinterpret_cast<const float4*>(x)[0];
            const float4 xv1 = reinterpret_cast<const float4*>(x)[1];
            const int rows[3] = { o, 100 + o, 150 + o };   // i, g, o rows
            float gv[3];
            #pragma unroll
            for (int k = 0; k < 3; ++k) {
                const int row = rows[k];
                const float4* __restrict__ w = reinterpret_cast<const float4*>(W_ih_opp + row * 8);
                float acc = b_ih_opp[row] + b_hh_opp[row];
                const float4 a = w[0], b = w[1];
                acc = fmaf(a.x, xv0.x, acc); acc = fmaf(a.y, xv0.y, acc);
                acc = fmaf(a.z, xv0.z, acc); acc = fmaf(a.w, xv0.w, acc);
                acc = fmaf(b.x, xv1.x, acc); acc = fmaf(b.y, xv1.y, acc);
                acc = fmaf(b.z, xv1.z, acc); acc = fmaf(b.w, xv1.w, acc);
                gv[k] = acc;
            }
            const float c2 = sigmoid_f(gv[0]) * tanh_f(gv[1]);
            s_feat[100 + o] = sigmoid_f(gv[2]) * tanh_f(c2);
        }
    } else if (warp < 11) {
        // ---- v-half0: sum_{m=0}^{37} W2[m]*W1[m,i], FULL unroll ----
        const int i = tid - 192;
        if (i < 150) {
            const float* __restrict__ w1c = W1 + i;
            float acc = 0.0f;
            #pragma unroll
            for (int m = 0; m < 38; ++m)
                acc = fmaf(__ldg(W2 + m), w1c[m * 150], acc);
            s_v0[i] = acc;
        }
    } else if (warp < 16) {
        // ---- v-half1: sum_{m=38}^{74} W2[m]*W1[m,i], FULL unroll ----
        const int i = tid - 352;
        if (i < 150) {
            const float* __restrict__ w1c = W1 + 38 * 150 + i;
            float acc = 0.0f;
            #pragma unroll
            for (int m = 0; m < 37; ++m)
                acc = fmaf(__ldg(W2 + 38 + m), w1c[m * 150], acc);
            s_v1[i] = acc;
        }
    } else {
        // ---- warp 16: c = W2.b1 + b2, kept in registers ----
        float acc = 0.0f;
        #pragma unroll
        for (int m = lane; m < 75; m += 32)
            acc = fmaf(W2[m], b1[m], acc);
        c_reg = warp_sum(acc) + __ldg(b2);
    }
    __syncthreads();

    // ---- tail: out = sum_i (v0[i]+v1[i])*feat[i] + c   (warp 16) ----
    if (warp == 16) {
        float acc = 0.0f;
        #pragma unroll
        for (int i = lane; i < 150; i += 32)
            acc = fmaf(s_v0[i] + s_v1[i], s_feat[i], acc);
        acc = warp_sum(acc);
        if (lane == 0) out[0] = acc + c_reg;
    }
}

extern "C" void kernel_launch(void* const* d_in, const int* in_sizes, int n_in,
                              void* d_out, int out_size)
{
    const float* x        = (const float*)d_in[0];
    const float* h0_gen   = (const float*)d_in[1];
    const float* c0_gen   = (const float*)d_in[2];
    const float* W_ih_opp = (const float*)d_in[3];
    // d_in[4] = W_hh_opp — unused (zero initial state)
    const float* b_ih_opp = (const float*)d_in[5];
    const float* b_hh_opp = (const float*)d_in[6];
    const float* W_ih_gen = (const float*)d_in[7];
    const float* W_hh_gen = (const float*)d_in[8];
    const float* b_ih_gen = (const float*)d_in[9];
    const float* b_hh_gen = (const float*)d_in[10];
    const float* W1       = (const float*)d_in[11];
    const float* b1       = (const float*)d_in[12];
    const float* W2       = (const float*)d_in[13];
    const float* b2       = (const float*)d_in[14];
    float* out = (float*)d_out;

    net_kernel<<<1, 544>>>(x, h0_gen, c0_gen, W_ih_opp, b_ih_opp, b_hh_opp,
                           W_ih_gen, W_hh_gen, b_ih_gen, b_hh_gen,
                           W1, b1, W2, b2, out);
}